// round 16
// baseline (speedup 1.0000x reference)
#include <cuda_runtime.h>
#include <cuda_fp16.h>
#include <cstdint>
#include <math.h>

// Inputs: a [4096,128] f32, p [4096,128] f32, n [4096,128] f32. Output: 1 f32.

#define B_SIZE 4096
#define DIM    128
#define NTOT   12288
#define NTILES 96
#define TPB    256
#define MARGIN 0.4f
#define ALPHA  0.01f

// ---- smem layout (bytes) ----
#define OFF_SQJH(b) ((b) * 256)          // fp16 sqj, per buffer
#define OFF_A       1024
#define OFF_B(b)    (OFF_A + 32768 + (b) * 32768)
#define SMEM_TOTAL  (OFF_A + 32768 + 2 * 32768)   // 99328

// ---- device scratch ----
__device__ float         g_sq[NTOT];
__device__ __half        g_sqh[NTOT];
__device__ unsigned int  g_rowmin[NTOT];
__device__ float         g_posmax[NTOT];
__device__ float         g_regpart[B_SIZE];
__device__ __half        g_h[NTOT * DIM];

// ---- helpers ----
__device__ __forceinline__ uint32_t smem_u32(const void* p) {
    uint32_t a;
    asm("{ .reg .u64 t; cvta.to.shared.u64 t, %1; cvt.u32.u64 %0, t; }"
        : "=r"(a) : "l"(p));
    return a;
}
__device__ __forceinline__ void cp16(uint32_t dst, const void* src) {
    asm volatile("cp.async.cg.shared.global [%0], [%1], 16;"
                 :: "r"(dst), "l"(src));
}
#define CP_COMMIT() asm volatile("cp.async.commit_group;" ::: "memory")
#define CP_WAIT(n)  asm volatile("cp.async.wait_group %0;" :: "n"(n) : "memory")

__device__ __forceinline__ void ldsm4(uint32_t* r, uint32_t addr) {
    asm volatile("ldmatrix.sync.aligned.m8n8.x4.shared.b16 {%0,%1,%2,%3}, [%4];"
                 : "=r"(r[0]), "=r"(r[1]), "=r"(r[2]), "=r"(r[3]) : "r"(addr));
}
__device__ __forceinline__ void mma16816h(uint32_t* d, const uint32_t* a,
                                          uint32_t b0, uint32_t b1) {
    asm volatile("mma.sync.aligned.m16n8k16.row.col.f16.f16.f16.f16 "
                 "{%0,%1}, {%2,%3,%4,%5}, {%6,%7}, {%0,%1};"
                 : "+r"(d[0]), "+r"(d[1])
                 : "r"(a[0]), "r"(a[1]), "r"(a[2]), "r"(a[3]),
                   "r"(b0), "r"(b1));
}
__device__ __forceinline__ __half2 shfl_hmin2(__half2 v, int ofs) {
    uint32_t u = __shfl_xor_sync(0xffffffffu,
                                 *reinterpret_cast<uint32_t*>(&v), ofs);
    return __hmin2(v, *reinterpret_cast<__half2*>(&u));
}

// ---------------------------------------------------------------------------
// prep: one warp per column c; 7 reduction chains + fp16 conversion.
// ---------------------------------------------------------------------------
__global__ void __launch_bounds__(256) prep_kernel(const float* __restrict__ a,
                                                   const float* __restrict__ p,
                                                   const float* __restrict__ n) {
    int c    = (blockIdx.x * 256 + threadIdx.x) >> 5;
    int lane = threadIdx.x & 31;

    float4 xa = reinterpret_cast<const float4*>(a + (size_t)c * DIM)[lane];
    float4 xp = reinterpret_cast<const float4*>(p + (size_t)c * DIM)[lane];
    float4 xn = reinterpret_cast<const float4*>(n + (size_t)c * DIM)[lane];

    float as[4] = {xa.x, xa.y, xa.z, xa.w};
    float ps[4] = {xp.x, xp.y, xp.z, xp.w};
    float ns[4] = {xn.x, xn.y, xn.z, xn.w};

    float sqa = 0.f, sqp = 0.f, sqn = 0.f;
    float reg = 0.f;
    float eap = 0.f, ean = 0.f, epn = 0.f;
    #pragma unroll
    for (int i = 0; i < 4; i++) {
        sqa += as[i] * as[i];  sqp += ps[i] * ps[i];  sqn += ns[i] * ns[i];
        float ta = fabsf(as[i]) - 1.f;
        float tp = fabsf(ps[i]) - 1.f;
        float tn = fabsf(ns[i]) - 1.f;
        reg += ta * ta + tp * tp + tn * tn;
        float d1 = as[i] - ps[i]; eap += d1 * d1;
        float d2 = as[i] - ns[i]; ean += d2 * d2;
        float d3 = ps[i] - ns[i]; epn += d3 * d3;
    }
    #pragma unroll
    for (int ofs = 16; ofs; ofs >>= 1) {
        sqa += __shfl_xor_sync(0xffffffffu, sqa, ofs);
        sqp += __shfl_xor_sync(0xffffffffu, sqp, ofs);
        sqn += __shfl_xor_sync(0xffffffffu, sqn, ofs);
        reg += __shfl_xor_sync(0xffffffffu, reg, ofs);
        eap += __shfl_xor_sync(0xffffffffu, eap, ofs);
        ean += __shfl_xor_sync(0xffffffffu, ean, ofs);
        epn += __shfl_xor_sync(0xffffffffu, epn, ofs);
    }
    if (lane == 0) {
        g_sq[c]              = sqa;
        g_sq[c + B_SIZE]     = sqp;
        g_sq[c + 2 * B_SIZE] = sqn;
        g_sqh[c]              = __float2half_rn(sqa);
        g_sqh[c + B_SIZE]     = __float2half_rn(sqp);
        g_sqh[c + 2 * B_SIZE] = __float2half_rn(sqn);
        g_regpart[c]          = reg;
        g_posmax[c]               = fmaxf(eap, ean);
        g_posmax[c + B_SIZE]      = fmaxf(eap, epn);
        g_posmax[c + 2 * B_SIZE]  = fmaxf(ean, epn);
        g_rowmin[c]               = 0x7f800000u;
        g_rowmin[c + B_SIZE]      = 0x7f800000u;
        g_rowmin[c + 2 * B_SIZE]  = 0x7f800000u;
    }

    #pragma unroll
    for (int seg = 0; seg < 3; seg++) {
        const float* s = (seg == 0) ? as : (seg == 1) ? ps : ns;
        unsigned h0 = 0, h1 = 0;
        #pragma unroll
        for (int i = 0; i < 4; i++) {
            unsigned hb = __half_as_ushort(__float2half_rn(s[i]));
            if (i < 2) h0 |= hb << (16 * i);
            else       h1 |= hb << (16 * (i - 2));
        }
        reinterpret_cast<uint2*>(g_h)[(c + seg * B_SIZE) * 32 + lane] =
            make_uint2(h0, h1);
    }
}

// ---------------------------------------------------------------------------
__device__ __forceinline__ void prefetch_tile(const __half* __restrict__ g,
                                              int rowbase, uint32_t sm_off,
                                              uint32_t sb, int tid) {
    const uint4* src = reinterpret_cast<const uint4*>(g) + (size_t)rowbase * 16;
    #pragma unroll
    for (int i = 0; i < 8; i++) {
        int ch = tid + i * 256;
        int m = ch >> 4, c = ch & 15;
        uint32_t dst = sb + sm_off + ((uint32_t)m << 8) + ((uint32_t)(c ^ (m & 7)) << 4);
        cp16(dst, src + ch);
    }
}
__device__ __forceinline__ void stage_sqh(uint32_t sb, int buf, int jt, int tid) {
    if (tid < 16) cp16(sb + OFF_SQJH(buf) + tid * 16, g_sqh + jt * 128 + tid * 8);
}

// ---------------------------------------------------------------------------
// MMA of one 128x128 tile into acc (zero-init inside).
// ---------------------------------------------------------------------------
__device__ __forceinline__ void mma_tile(uint32_t Ab, uint32_t Bb,
        int m0w, int n0w, int a_rbit, int a_cbit, int b_rbit, int b_cbit,
        int l7, uint32_t (*acc)[4][2]) {
    #pragma unroll
    for (int mt = 0; mt < 4; mt++)
        #pragma unroll
        for (int nt = 0; nt < 4; nt++) { acc[mt][nt][0] = 0u; acc[mt][nt][1] = 0u; }

    #pragma unroll
    for (int ks = 0; ks < 8; ks++) {
        const int c0 = ks * 2;
        uint32_t af[4][4], bf[2][4];
        #pragma unroll
        for (int mt = 0; mt < 4; mt++) {
            int row = m0w + mt * 16 + l7 + a_rbit * 8;
            ldsm4(af[mt], Ab + ((uint32_t)row << 8) +
                          ((uint32_t)((c0 + a_cbit) ^ (row & 7)) << 4));
        }
        #pragma unroll
        for (int bt = 0; bt < 2; bt++) {
            int row = n0w + bt * 16 + l7 + b_rbit * 8;
            ldsm4(bf[bt], Bb + ((uint32_t)row << 8) +
                          ((uint32_t)((c0 + b_cbit) ^ (row & 7)) << 4));
        }
        #pragma unroll
        for (int mt = 0; mt < 4; mt++)
            #pragma unroll
            for (int nt = 0; nt < 4; nt++)
                mma16816h(acc[mt][nt], af[mt],
                          bf[nt >> 1][(nt & 1) * 2],
                          bf[nt >> 1][(nt & 1) * 2 + 1]);
    }
}

// ---------------------------------------------------------------------------
// epilogue of one finished tile (acc regs -> row/col running mins).
// ---------------------------------------------------------------------------
__device__ __forceinline__ void epi_tile(uint32_t (*acc)[4][2],
        const __half2* sj2, int bi, int jt, int m0w, int n0w, int lane,
        const __half2 (*sqi2)[2], float (*rmin)[2]) {
    const __half2 NEG2 = __float2half2_rn(-2.0f);
    const __half2 HINF2 = __half2half2(__ushort_as_half(0x7C00));

    if ((bi & 31) == (jt & 31)) {
        #pragma unroll
        for (int mt = 0; mt < 4; mt++) {
            const int r0 = m0w + mt * 16 + (lane >> 2);
            const int r1 = r0 + 8;
            #pragma unroll
            for (int nt = 0; nt < 4; nt++) {
                const int c0i = n0w + nt * 8 + (lane & 3) * 2;
                if (r0 == c0i)     acc[mt][nt][0] = (acc[mt][nt][0] & 0xFFFF0000u) | 0x0000FC00u;
                if (r0 == c0i + 1) acc[mt][nt][0] = (acc[mt][nt][0] & 0x0000FFFFu) | 0xFC000000u;
                if (r1 == c0i)     acc[mt][nt][1] = (acc[mt][nt][1] & 0xFFFF0000u) | 0x0000FC00u;
                if (r1 == c0i + 1) acc[mt][nt][1] = (acc[mt][nt][1] & 0x0000FFFFu) | 0xFC000000u;
            }
        }
    }

    __half2 rh2[4][2], ch2[4];
    #pragma unroll
    for (int mt = 0; mt < 4; mt++) { rh2[mt][0] = HINF2; rh2[mt][1] = HINF2; }
    #pragma unroll
    for (int nt = 0; nt < 4; nt++) ch2[nt] = HINF2;

    #pragma unroll
    for (int nt = 0; nt < 4; nt++) {
        #pragma unroll
        for (int mt = 0; mt < 4; mt++) {
            __half2 a0 = *reinterpret_cast<__half2*>(&acc[mt][nt][0]);
            __half2 a1 = *reinterpret_cast<__half2*>(&acc[mt][nt][1]);
            rh2[mt][0] = __hmin2(rh2[mt][0], __hfma2(a0, NEG2, sj2[nt]));
            rh2[mt][1] = __hmin2(rh2[mt][1], __hfma2(a1, NEG2, sj2[nt]));
            ch2[nt] = __hmin2(ch2[nt], __hfma2(a0, NEG2, sqi2[mt][0]));
            ch2[nt] = __hmin2(ch2[nt], __hfma2(a1, NEG2, sqi2[mt][1]));
        }
    }

    #pragma unroll
    for (int mt = 0; mt < 4; mt++)
        #pragma unroll
        for (int h = 0; h < 2; h++) {
            float2 f = __half22float2(rh2[mt][h]);
            rmin[mt][h] = fminf(rmin[mt][h], fminf(f.x, f.y));
        }

    #pragma unroll
    for (int nt = 0; nt < 4; nt++) {
        ch2[nt] = shfl_hmin2(ch2[nt], 4);
        ch2[nt] = shfl_hmin2(ch2[nt], 8);
        ch2[nt] = shfl_hmin2(ch2[nt], 16);
    }
    if (lane < 4) {
        #pragma unroll
        for (int nt = 0; nt < 4; nt++) {
            int c = n0w + nt * 8 + lane * 2;
            float2 sj = __ldg(reinterpret_cast<const float2*>(&g_sq[jt * 128 + c]));
            float2 f = __half22float2(ch2[nt]);
            float v0 = fmaxf(f.x + sj.x, 0.f);
            float v1 = fmaxf(f.y + sj.y, 0.f);
            atomicMin(&g_rowmin[jt * 128 + c],     __float_as_uint(v0));
            atomicMin(&g_rowmin[jt * 128 + c + 1], __float_as_uint(v1));
        }
    }
}

// ---------------------------------------------------------------------------
// tile kernel: software-pipelined — MMA(t) overlaps epilogue(t-1).
// ---------------------------------------------------------------------------
__global__ void __launch_bounds__(TPB, 2) tile_kernel() {
    extern __shared__ char smem[];
    uint32_t sb = smem_u32(smem);
    const int tid  = threadIdx.x;
    const int wid  = tid >> 5;
    const int lane = tid & 31;

    const int bi   = blockIdx.x / 3;
    const int grp  = blockIdx.x % 3;
    const int d0   = grp * 16;
    const int ntl  = 16 + ((grp == 2 && bi < 48) ? 1 : 0);
    const int rowbase = bi * 128;

    const int wy  = wid & 1,  wx = wid >> 1;
    const int m0w = wy * 64,  n0w = wx * 32;

    const int bj0 = (bi + d0) % NTILES;
    prefetch_tile(g_h, rowbase, OFF_A, sb, tid);
    prefetch_tile(g_h, bj0 * 128, OFF_B(0), sb, tid);
    stage_sqh(sb, 0, bj0, tid);
    CP_COMMIT();

    __half2 sqi2[4][2];
    float   rmin[4][2];
    #pragma unroll
    for (int mt = 0; mt < 4; mt++)
        #pragma unroll
        for (int h = 0; h < 2; h++) {
            int r = m0w + mt * 16 + (lane >> 2) + h * 8;
            sqi2[mt][h] = __float2half2_rn(g_sq[rowbase + r]);
            rmin[mt][h] = __int_as_float(0x7f800000);
        }

    const int a_rbit = (lane >> 3) & 1;
    const int a_cbit = (lane >> 4) & 1;
    const int b_rbit = (lane >> 4) & 1;
    const int b_cbit = (lane >> 3) & 1;
    const int l7 = lane & 7;
    const uint32_t Ab = sb + OFF_A;
    const int sjidx = n0w / 2 + (lane & 3);   // __half2 index base per warp

    uint32_t accA[4][4][2], accB[4][4][2];
    __half2  sjA[4], sjB[4];

    // ---- prologue: tile 0 -> accA ----
    CP_WAIT(0);
    __syncthreads();
    {
        const __half2* sqjh = reinterpret_cast<const __half2*>(smem + OFF_SQJH(0));
        #pragma unroll
        for (int nt = 0; nt < 4; nt++) sjA[nt] = sqjh[sjidx + nt * 4];
    }
    if (1 < ntl) {
        const int jn = (bi + d0 + 1) % NTILES;
        prefetch_tile(g_h, jn * 128, OFF_B(1), sb, tid);
        stage_sqh(sb, 1, jn, tid);
        CP_COMMIT();
    }
    mma_tile(Ab, sb + OFF_B(0), m0w, n0w, a_rbit, a_cbit, b_rbit, b_cbit, l7, accA);

    // ---- steady state: pairs (odd -> accB, even -> accA) ----
    int t = 1;
    while (t < ntl) {
        // odd t: MMA -> accB, epilogue(t-1) from accA
        {
            const int b = t & 1, nb = b ^ 1;
            CP_WAIT(0);
            __syncthreads();
            const __half2* sqjh = reinterpret_cast<const __half2*>(smem + OFF_SQJH(b));
            #pragma unroll
            for (int nt = 0; nt < 4; nt++) sjB[nt] = sqjh[sjidx + nt * 4];
            if (t + 1 < ntl) {
                const int jn = (bi + d0 + t + 1) % NTILES;
                prefetch_tile(g_h, jn * 128, OFF_B(nb), sb, tid);
                stage_sqh(sb, nb, jn, tid);
                CP_COMMIT();
            }
            mma_tile(Ab, sb + OFF_B(b), m0w, n0w, a_rbit, a_cbit, b_rbit, b_cbit, l7, accB);
            epi_tile(accA, sjA, bi, (bi + d0 + t - 1) % NTILES, m0w, n0w, lane, sqi2, rmin);
        }
        t++;
        if (t >= ntl) break;
        // even t: MMA -> accA, epilogue(t-1) from accB
        {
            const int b = t & 1, nb = b ^ 1;
            CP_WAIT(0);
            __syncthreads();
            const __half2* sqjh = reinterpret_cast<const __half2*>(smem + OFF_SQJH(b));
            #pragma unroll
            for (int nt = 0; nt < 4; nt++) sjA[nt] = sqjh[sjidx + nt * 4];
            if (t + 1 < ntl) {
                const int jn = (bi + d0 + t + 1) % NTILES;
                prefetch_tile(g_h, jn * 128, OFF_B(nb), sb, tid);
                stage_sqh(sb, nb, jn, tid);
                CP_COMMIT();
            }
            mma_tile(Ab, sb + OFF_B(b), m0w, n0w, a_rbit, a_cbit, b_rbit, b_cbit, l7, accA);
            epi_tile(accB, sjB, bi, (bi + d0 + t - 1) % NTILES, m0w, n0w, lane, sqi2, rmin);
        }
        t++;
    }

    // ---- drain: epilogue of the last tile ----
    {
        const int tl = ntl - 1;
        const int jt = (bi + d0 + tl) % NTILES;
        if (tl & 1) epi_tile(accB, sjB, bi, jt, m0w, n0w, lane, sqi2, rmin);
        else        epi_tile(accA, sjA, bi, jt, m0w, n0w, lane, sqi2, rmin);
    }

    // ---- final row-min ----
    #pragma unroll
    for (int mt = 0; mt < 4; mt++)
        #pragma unroll
        for (int h = 0; h < 2; h++) {
            float v = rmin[mt][h];
            v = fminf(v, __shfl_xor_sync(0xffffffffu, v, 1));
            v = fminf(v, __shfl_xor_sync(0xffffffffu, v, 2));
            if ((lane & 3) == 0) {
                int r = m0w + mt * 16 + (lane >> 2) + h * 8;
                float d2 = fmaxf(v + g_sq[rowbase + r], 0.f);
                atomicMin(&g_rowmin[rowbase + r], __float_as_uint(d2));
            }
        }
}

// ---------------------------------------------------------------------------
__global__ void finalize_kernel(float* __restrict__ out) {
    __shared__ float sl[1024];
    __shared__ float sr[1024];
    int t = threadIdx.x;
    float ls = 0.0f, rs = 0.0f;
    for (int i = t; i < NTOT; i += 1024) {
        float pm = g_posmax[i];
        float nm = __uint_as_float(g_rowmin[i]);
        float pd = (pm > 0.0f) ? sqrtf(pm) : 0.0f;
        float nd = (nm > 0.0f) ? sqrtf(nm) : 0.0f;
        ls += fmaxf(pd - nd + MARGIN, 0.0f);
    }
    for (int i = t; i < B_SIZE; i += 1024) rs += g_regpart[i];
    sl[t] = ls; sr[t] = rs;
    __syncthreads();
    #pragma unroll
    for (int s = 512; s; s >>= 1) {
        if (t < s) { sl[t] += sl[t + s]; sr[t] += sr[t + s]; }
        __syncthreads();
    }
    if (t == 0)
        out[0] = sl[0] / (float)NTOT + ALPHA * (sr[0] / (float)(NTOT * DIM));
}

// ---------------------------------------------------------------------------
extern "C" void kernel_launch(void* const* d_in, const int* in_sizes, int n_in,
                              void* d_out, int out_size) {
    const float* a = (const float*)d_in[0];
    const float* p = (const float*)d_in[1];
    const float* n = (const float*)d_in[2];
    float* out = (float*)d_out;

    cudaFuncSetAttribute(tile_kernel,
                         cudaFuncAttributeMaxDynamicSharedMemorySize, SMEM_TOTAL);

    prep_kernel<<<B_SIZE / 8, 256>>>(a, p, n);
    tile_kernel<<<NTILES * 3, TPB, SMEM_TOTAL>>>();
    finalize_kernel<<<1, 1024>>>(out);
}

// round 17
// speedup vs baseline: 1.0620x; 1.0620x over previous
#include <cuda_runtime.h>
#include <cuda_fp16.h>
#include <cstdint>
#include <math.h>

// Inputs: a [4096,128] f32, p [4096,128] f32, n [4096,128] f32. Output: 1 f32.

#define B_SIZE 4096
#define DIM    128
#define NTOT   12288
#define NTILES 96
#define TPB    128
#define MARGIN 0.4f
#define ALPHA  0.01f

// ---- smem layout (bytes) ----
#define OFF_SQJ(b)  ((b) * 512)          // fp32 sqj, per buffer
#define OFF_SQJH(b) (1024 + (b) * 256)   // fp16 sqj, per buffer
#define OFF_A       2048
#define OFF_B(b)    (OFF_A + 32768 + (b) * 32768)
#define SMEM_TOTAL  (OFF_A + 32768 + 2 * 32768)   // 100352

// ---- device scratch ----
__device__ float         g_sq[NTOT];
__device__ __half        g_sqh[NTOT];
__device__ unsigned int  g_rowmin[NTOT];
__device__ float         g_posmax[NTOT];
__device__ float         g_regpart[B_SIZE];
__device__ __half        g_h[NTOT * DIM];

// ---- helpers ----
__device__ __forceinline__ uint32_t smem_u32(const void* p) {
    uint32_t a;
    asm("{ .reg .u64 t; cvta.to.shared.u64 t, %1; cvt.u32.u64 %0, t; }"
        : "=r"(a) : "l"(p));
    return a;
}
__device__ __forceinline__ void cp16(uint32_t dst, const void* src) {
    asm volatile("cp.async.cg.shared.global [%0], [%1], 16;"
                 :: "r"(dst), "l"(src));
}
#define CP_COMMIT() asm volatile("cp.async.commit_group;" ::: "memory")
#define CP_WAIT(n)  asm volatile("cp.async.wait_group %0;" :: "n"(n) : "memory")

__device__ __forceinline__ void ldsm4(uint32_t* r, uint32_t addr) {
    asm volatile("ldmatrix.sync.aligned.m8n8.x4.shared.b16 {%0,%1,%2,%3}, [%4];"
                 : "=r"(r[0]), "=r"(r[1]), "=r"(r[2]), "=r"(r[3]) : "r"(addr));
}
__device__ __forceinline__ void mma16816h(uint32_t* d, const uint32_t* a,
                                          uint32_t b0, uint32_t b1) {
    asm volatile("mma.sync.aligned.m16n8k16.row.col.f16.f16.f16.f16 "
                 "{%0,%1}, {%2,%3,%4,%5}, {%6,%7}, {%0,%1};"
                 : "+r"(d[0]), "+r"(d[1])
                 : "r"(a[0]), "r"(a[1]), "r"(a[2]), "r"(a[3]),
                   "r"(b0), "r"(b1));
}
__device__ __forceinline__ __half2 shfl_hmin2(__half2 v, int ofs) {
    uint32_t u = __shfl_xor_sync(0xffffffffu,
                                 *reinterpret_cast<uint32_t*>(&v), ofs);
    return __hmin2(v, *reinterpret_cast<__half2*>(&u));
}

// ---------------------------------------------------------------------------
// prep: one warp per column c; 7 reduction chains + fp16 conversion.
// ---------------------------------------------------------------------------
__global__ void __launch_bounds__(256) prep_kernel(const float* __restrict__ a,
                                                   const float* __restrict__ p,
                                                   const float* __restrict__ n) {
    int c    = (blockIdx.x * 256 + threadIdx.x) >> 5;
    int lane = threadIdx.x & 31;

    float4 xa = reinterpret_cast<const float4*>(a + (size_t)c * DIM)[lane];
    float4 xp = reinterpret_cast<const float4*>(p + (size_t)c * DIM)[lane];
    float4 xn = reinterpret_cast<const float4*>(n + (size_t)c * DIM)[lane];

    float as[4] = {xa.x, xa.y, xa.z, xa.w};
    float ps[4] = {xp.x, xp.y, xp.z, xp.w};
    float ns[4] = {xn.x, xn.y, xn.z, xn.w};

    float sqa = 0.f, sqp = 0.f, sqn = 0.f;
    float reg = 0.f;
    float eap = 0.f, ean = 0.f, epn = 0.f;
    #pragma unroll
    for (int i = 0; i < 4; i++) {
        sqa += as[i] * as[i];  sqp += ps[i] * ps[i];  sqn += ns[i] * ns[i];
        float ta = fabsf(as[i]) - 1.f;
        float tp = fabsf(ps[i]) - 1.f;
        float tn = fabsf(ns[i]) - 1.f;
        reg += ta * ta + tp * tp + tn * tn;
        float d1 = as[i] - ps[i]; eap += d1 * d1;
        float d2 = as[i] - ns[i]; ean += d2 * d2;
        float d3 = ps[i] - ns[i]; epn += d3 * d3;
    }
    #pragma unroll
    for (int ofs = 16; ofs; ofs >>= 1) {
        sqa += __shfl_xor_sync(0xffffffffu, sqa, ofs);
        sqp += __shfl_xor_sync(0xffffffffu, sqp, ofs);
        sqn += __shfl_xor_sync(0xffffffffu, sqn, ofs);
        reg += __shfl_xor_sync(0xffffffffu, reg, ofs);
        eap += __shfl_xor_sync(0xffffffffu, eap, ofs);
        ean += __shfl_xor_sync(0xffffffffu, ean, ofs);
        epn += __shfl_xor_sync(0xffffffffu, epn, ofs);
    }
    if (lane == 0) {
        g_sq[c]              = sqa;
        g_sq[c + B_SIZE]     = sqp;
        g_sq[c + 2 * B_SIZE] = sqn;
        g_sqh[c]              = __float2half_rn(sqa);
        g_sqh[c + B_SIZE]     = __float2half_rn(sqp);
        g_sqh[c + 2 * B_SIZE] = __float2half_rn(sqn);
        g_regpart[c]          = reg;
        g_posmax[c]               = fmaxf(eap, ean);
        g_posmax[c + B_SIZE]      = fmaxf(eap, epn);
        g_posmax[c + 2 * B_SIZE]  = fmaxf(ean, epn);
        g_rowmin[c]               = 0x7f800000u;
        g_rowmin[c + B_SIZE]      = 0x7f800000u;
        g_rowmin[c + 2 * B_SIZE]  = 0x7f800000u;
    }

    #pragma unroll
    for (int seg = 0; seg < 3; seg++) {
        const float* s = (seg == 0) ? as : (seg == 1) ? ps : ns;
        unsigned h0 = 0, h1 = 0;
        #pragma unroll
        for (int i = 0; i < 4; i++) {
            unsigned hb = __half_as_ushort(__float2half_rn(s[i]));
            if (i < 2) h0 |= hb << (16 * i);
            else       h1 |= hb << (16 * (i - 2));
        }
        reinterpret_cast<uint2*>(g_h)[(c + seg * B_SIZE) * 32 + lane] =
            make_uint2(h0, h1);
    }
}

// ---------------------------------------------------------------------------
__device__ __forceinline__ void prefetch_tile(const __half* __restrict__ g,
                                              int rowbase, uint32_t sm_off,
                                              uint32_t sb, int tid) {
    const uint4* src = reinterpret_cast<const uint4*>(g) + (size_t)rowbase * 16;
    #pragma unroll
    for (int ch = tid; ch < 2048; ch += TPB) {
        int m = ch >> 4, c = ch & 15;
        uint32_t dst = sb + sm_off + ((uint32_t)m << 8) + ((uint32_t)(c ^ (m & 7)) << 4);
        cp16(dst, src + ch);
    }
}
__device__ __forceinline__ void stage_sq(uint32_t sb, int buf, int jt, int tid) {
    if (tid < 32) cp16(sb + OFF_SQJ(buf) + tid * 16, g_sq + jt * 128 + tid * 4);
    else if (tid < 48)
        cp16(sb + OFF_SQJH(buf) + (tid - 32) * 16, g_sqh + jt * 128 + (tid - 32) * 8);
}

// ---------------------------------------------------------------------------
// tile kernel: 128 threads, 4 warps, warp tile 64x64 (2M x 2N).
// Single barrier per tile, direct global col-min atomics (round-14 skeleton).
// ---------------------------------------------------------------------------
__global__ void __launch_bounds__(TPB, 2) tile_kernel() {
    extern __shared__ char smem[];
    uint32_t sb = smem_u32(smem);
    const int tid  = threadIdx.x;
    const int wid  = tid >> 5;
    const int lane = tid & 31;

    const int bi   = blockIdx.x / 3;
    const int grp  = blockIdx.x % 3;
    const int d0   = grp * 16;
    const int ntl  = 16 + ((grp == 2 && bi < 48) ? 1 : 0);
    const int rowbase = bi * 128;

    // warp layout: 2 warps in M (64 rows) x 2 warps in N (64 cols)
    const int m0w = (wid & 1) * 64;
    const int n0w = (wid >> 1) * 64;

    const int bj0 = (bi + d0) % NTILES;
    prefetch_tile(g_h, rowbase, OFF_A, sb, tid);
    prefetch_tile(g_h, bj0 * 128, OFF_B(0), sb, tid);
    stage_sq(sb, 0, bj0, tid);
    CP_COMMIT();

    __half2 sqi2[4][2];
    float   rmin[4][2];
    #pragma unroll
    for (int mt = 0; mt < 4; mt++)
        #pragma unroll
        for (int h = 0; h < 2; h++) {
            int r = m0w + mt * 16 + (lane >> 2) + h * 8;
            sqi2[mt][h] = __float2half2_rn(g_sq[rowbase + r]);
            rmin[mt][h] = __int_as_float(0x7f800000);
        }

    const int a_rbit = (lane >> 3) & 1;
    const int a_cbit = (lane >> 4) & 1;
    const int b_rbit = (lane >> 4) & 1;
    const int b_cbit = (lane >> 3) & 1;
    const int l7 = lane & 7;
    const __half2 NEG2 = __float2half2_rn(-2.0f);
    const __half2 HINF2 = __half2half2(__ushort_as_half(0x7C00));

    for (int t = 0; t < ntl; t++) {
        const int b  = t & 1, nb = b ^ 1;
        const int jt = (bi + d0 + t) % NTILES;

        CP_WAIT(0);
        __syncthreads();   // single barrier: buf b ready, everyone done with nb

        // hoist sqj into registers
        __half2 sj2r[8];
        {
            const __half2* sqjh = reinterpret_cast<const __half2*>(smem + OFF_SQJH(b));
            #pragma unroll
            for (int nt = 0; nt < 8; nt++)
                sj2r[nt] = sqjh[(n0w + nt * 8) / 2 + (lane & 3)];
        }
        float2 sqjf2[8];
        if (lane < 4) {
            const float* sqjf = reinterpret_cast<const float*>(smem + OFF_SQJ(b));
            #pragma unroll
            for (int nt = 0; nt < 8; nt++)
                sqjf2[nt] = *reinterpret_cast<const float2*>(&sqjf[n0w + nt * 8 + lane * 2]);
        }

        if (t + 1 < ntl) {
            const int jn = (bi + d0 + t + 1) % NTILES;
            prefetch_tile(g_h, jn * 128, OFF_B(nb), sb, tid);
            stage_sq(sb, nb, jn, tid);
            CP_COMMIT();
        }

        // ---- MMA: warp tile 64x64, K=128 ----
        uint32_t acc[4][8][2];
        #pragma unroll
        for (int mt = 0; mt < 4; mt++)
            #pragma unroll
            for (int nt = 0; nt < 8; nt++) { acc[mt][nt][0] = 0u; acc[mt][nt][1] = 0u; }

        const uint32_t Ab = sb + OFF_A, Bb = sb + OFF_B(b);

        #pragma unroll
        for (int ks = 0; ks < 8; ks++) {
            const int c0 = ks * 2;
            uint32_t af[4][4], bf[4][4];
            #pragma unroll
            for (int mt = 0; mt < 4; mt++) {
                int row = m0w + mt * 16 + l7 + a_rbit * 8;
                ldsm4(af[mt], Ab + ((uint32_t)row << 8) +
                              ((uint32_t)((c0 + a_cbit) ^ (row & 7)) << 4));
            }
            #pragma unroll
            for (int bt = 0; bt < 4; bt++) {
                int row = n0w + bt * 16 + l7 + b_rbit * 8;
                ldsm4(bf[bt], Bb + ((uint32_t)row << 8) +
                              ((uint32_t)((c0 + b_cbit) ^ (row & 7)) << 4));
            }
            #pragma unroll
            for (int mt = 0; mt < 4; mt++)
                #pragma unroll
                for (int nt = 0; nt < 8; nt++)
                    mma16816h(acc[mt][nt], af[mt],
                              bf[nt >> 1][(nt & 1) * 2],
                              bf[nt >> 1][(nt & 1) * 2 + 1]);
        }

        // ---- diag mask ----
        if ((bi & 31) == (jt & 31)) {
            #pragma unroll
            for (int mt = 0; mt < 4; mt++) {
                const int r0 = m0w + mt * 16 + (lane >> 2);
                const int r1 = r0 + 8;
                #pragma unroll
                for (int nt = 0; nt < 8; nt++) {
                    const int c0i = n0w + nt * 8 + (lane & 3) * 2;
                    if (r0 == c0i)     acc[mt][nt][0] = (acc[mt][nt][0] & 0xFFFF0000u) | 0x0000FC00u;
                    if (r0 == c0i + 1) acc[mt][nt][0] = (acc[mt][nt][0] & 0x0000FFFFu) | 0xFC000000u;
                    if (r1 == c0i)     acc[mt][nt][1] = (acc[mt][nt][1] & 0xFFFF0000u) | 0x0000FC00u;
                    if (r1 == c0i + 1) acc[mt][nt][1] = (acc[mt][nt][1] & 0x0000FFFFu) | 0xFC000000u;
                }
            }
        }

        // ---- packed epilogue ----
        __half2 rh2[4][2], ch2[8];
        #pragma unroll
        for (int mt = 0; mt < 4; mt++) { rh2[mt][0] = HINF2; rh2[mt][1] = HINF2; }
        #pragma unroll
        for (int nt = 0; nt < 8; nt++) ch2[nt] = HINF2;

        #pragma unroll
        for (int nt = 0; nt < 8; nt++) {
            #pragma unroll
            for (int mt = 0; mt < 4; mt++) {
                __half2 a0 = *reinterpret_cast<__half2*>(&acc[mt][nt][0]);
                __half2 a1 = *reinterpret_cast<__half2*>(&acc[mt][nt][1]);
                rh2[mt][0] = __hmin2(rh2[mt][0], __hfma2(a0, NEG2, sj2r[nt]));
                rh2[mt][1] = __hmin2(rh2[mt][1], __hfma2(a1, NEG2, sj2r[nt]));
                ch2[nt] = __hmin2(ch2[nt], __hfma2(a0, NEG2, sqi2[mt][0]));
                ch2[nt] = __hmin2(ch2[nt], __hfma2(a1, NEG2, sqi2[mt][1]));
            }
        }

        #pragma unroll
        for (int mt = 0; mt < 4; mt++)
            #pragma unroll
            for (int h = 0; h < 2; h++) {
                float2 f = __half22float2(rh2[mt][h]);
                rmin[mt][h] = fminf(rmin[mt][h], fminf(f.x, f.y));
            }

        #pragma unroll
        for (int nt = 0; nt < 8; nt++) {
            ch2[nt] = shfl_hmin2(ch2[nt], 4);
            ch2[nt] = shfl_hmin2(ch2[nt], 8);
            ch2[nt] = shfl_hmin2(ch2[nt], 16);
        }
        if (lane < 4) {
            #pragma unroll
            for (int nt = 0; nt < 8; nt++) {
                int c = n0w + nt * 8 + lane * 2;
                float2 f = __half22float2(ch2[nt]);
                float v0 = fmaxf(f.x + sqjf2[nt].x, 0.f);
                float v1 = fmaxf(f.y + sqjf2[nt].y, 0.f);
                atomicMin(&g_rowmin[jt * 128 + c],     __float_as_uint(v0));
                atomicMin(&g_rowmin[jt * 128 + c + 1], __float_as_uint(v1));
            }
        }
        // no trailing barrier
    }

    // ---- final row-min ----
    #pragma unroll
    for (int mt = 0; mt < 4; mt++)
        #pragma unroll
        for (int h = 0; h < 2; h++) {
            float v = rmin[mt][h];
            v = fminf(v, __shfl_xor_sync(0xffffffffu, v, 1));
            v = fminf(v, __shfl_xor_sync(0xffffffffu, v, 2));
            if ((lane & 3) == 0) {
                int r = m0w + mt * 16 + (lane >> 2) + h * 8;
                float d2 = fmaxf(v + g_sq[rowbase + r], 0.f);
                atomicMin(&g_rowmin[rowbase + r], __float_as_uint(d2));
            }
        }
}

// ---------------------------------------------------------------------------
__global__ void finalize_kernel(float* __restrict__ out) {
    __shared__ float sl[1024];
    __shared__ float sr[1024];
    int t = threadIdx.x;
    float ls = 0.0f, rs = 0.0f;
    for (int i = t; i < NTOT; i += 1024) {
        float pm = g_posmax[i];
        float nm = __uint_as_float(g_rowmin[i]);
        float pd = (pm > 0.0f) ? sqrtf(pm) : 0.0f;
        float nd = (nm > 0.0f) ? sqrtf(nm) : 0.0f;
        ls += fmaxf(pd - nd + MARGIN, 0.0f);
    }
    for (int i = t; i < B_SIZE; i += 1024) rs += g_regpart[i];
    sl[t] = ls; sr[t] = rs;
    __syncthreads();
    #pragma unroll
    for (int s = 512; s; s >>= 1) {
        if (t < s) { sl[t] += sl[t + s]; sr[t] += sr[t + s]; }
        __syncthreads();
    }
    if (t == 0)
        out[0] = sl[0] / (float)NTOT + ALPHA * (sr[0] / (float)(NTOT * DIM));
}

// ---------------------------------------------------------------------------
extern "C" void kernel_launch(void* const* d_in, const int* in_sizes, int n_in,
                              void* d_out, int out_size) {
    const float* a = (const float*)d_in[0];
    const float* p = (const float*)d_in[1];
    const float* n = (const float*)d_in[2];
    float* out = (float*)d_out;

    cudaFuncSetAttribute(tile_kernel,
                         cudaFuncAttributeMaxDynamicSharedMemorySize, SMEM_TOTAL);

    prep_kernel<<<B_SIZE / 8, 256>>>(a, p, n);
    tile_kernel<<<NTILES * 3, TPB, SMEM_TOTAL>>>();
    finalize_kernel<<<1, 1024>>>(out);
}